// round 16
// baseline (speedup 1.0000x reference)
#include <cuda_runtime.h>
#include <cuda_bf16.h>
#include <cstdint>

// Grapher round 16: fragment-permuted X / W images so K2's MMA loop uses
// ld.shared.v4/v2 instead of 36 scalar lds per k-step.
//  K1 (128 x 1024): scan + means (+ weight cvt in blocks 0-37 / W1 prefetch) +
//     GEMM1 fp32 + pair build -> permuted X image (bf16 hi/lo).
//  K2 (128 x 608): cp.async Wm+X (group A), W2 (group B), tensor-core 2-layer
//     MLP, m16n8k16 x9 + k8 tail, 3-term hi/lo split.
//
// Permuted A layout (per term, per batch): for m-tile mt (0..3):
//   k16 step ks (0..8): u32 slot = mt*1216 + ks*128 + lane*4 + reg (reg=a0..a3)
//   k8 tail:            u32 slot = mt*1216 + 1152   + lane*2 + reg (reg=a0,a1)
//   element (row r16, col c): reg = (r16>=8) + 2*(kc>=8 [k16 only]),
//   lane = (r16&7)*4 + ((kc&7)>>1), u32 half = c&1.
// Permuted B layout (per term/layer): for n-tile j (0..18):
//   k16: slot = j*608 + ks*64 + lane*2 + reg (b0,b1); tail: j*608+576+lane.

#define B_   128
#define S_   1024
#define H_   768
#define C_   150
#define NN   8
#define SEPID 3

typedef unsigned long long u64;

#define W_IMG_HALF 23104          // 152*152 ushorts per region

__device__ __align__(16) unsigned short g_Wcvt[4 * W_IMG_HALF];
__device__ __align__(16) uint32_t g_Ximg[B_ * 9728];   // per batch: hi 4864 u32, lo 4864

// ---------------- helpers ----------------
__device__ __forceinline__ uint32_t sptr(const void* p) {
    return (uint32_t)__cvta_generic_to_shared(p);
}
__device__ __forceinline__ void cp16(uint32_t s, const void* g) {
    asm volatile("cp.async.ca.shared.global [%0], [%1], 16;" :: "r"(s), "l"(g));
}
#define CP_COMMIT() asm volatile("cp.async.commit_group;" ::: "memory")
#define CP_WAIT1()  asm volatile("cp.async.wait_group 1;" ::: "memory")
#define CP_WAIT0()  asm volatile("cp.async.wait_group 0;" ::: "memory")

__device__ __forceinline__ void ffma2(u64& d, u64 a, u64 b) {
    asm("fma.rn.f32x2 %0, %1, %2, %0;" : "+l"(d) : "l"(a), "l"(b));
}
__device__ __forceinline__ u64 add2(u64 a, u64 b) {
    u64 r; asm("add.rn.f32x2 %0, %1, %2;" : "=l"(r) : "l"(a), "l"(b)); return r;
}
__device__ __forceinline__ u64 dup2(float x) {
    u64 r; asm("mov.b64 %0, {%1, %1};" : "=l"(r) : "f"(x)); return r;
}
__device__ __forceinline__ void unpack2(u64 v, float& lo, float& hi) {
    asm("mov.b64 {%0, %1}, %2;" : "=f"(lo), "=f"(hi) : "l"(v));
}
__device__ __forceinline__ u64 lds64(uint32_t a) {
    u64 v; asm volatile("ld.shared.u64 %0, [%1];" : "=l"(v) : "r"(a)); return v;
}
__device__ __forceinline__ void lds_v2(uint32_t a, u64& x, u64& y) {
    asm volatile("ld.shared.v2.u64 {%0, %1}, [%2];" : "=l"(x), "=l"(y) : "r"(a));
}
__device__ __forceinline__ void sts64(uint32_t a, u64 v) {
    asm volatile("st.shared.u64 [%0], %1;" :: "r"(a), "l"(v) : "memory");
}
__device__ __forceinline__ uint32_t lds_u32(uint32_t a) {
    uint32_t v; asm volatile("ld.shared.b32 %0, [%1];" : "=r"(v) : "r"(a)); return v;
}
__device__ __forceinline__ void lds_v2u32(uint32_t a, uint32_t& x, uint32_t& y) {
    asm volatile("ld.shared.v2.b32 {%0, %1}, [%2];" : "=r"(x), "=r"(y) : "r"(a));
}
__device__ __forceinline__ void lds_v4u32(uint32_t a, uint32_t& x, uint32_t& y,
                                          uint32_t& z, uint32_t& w) {
    asm volatile("ld.shared.v4.b32 {%0, %1, %2, %3}, [%4];"
                 : "=r"(x), "=r"(y), "=r"(z), "=r"(w) : "r"(a));
}
__device__ __forceinline__ void sts_u32(uint32_t a, uint32_t v) {
    asm volatile("st.shared.b32 [%0], %1;" :: "r"(a), "r"(v) : "memory");
}
__device__ __forceinline__ unsigned short f2bf(float x) {
    __nv_bfloat16 h = __float2bfloat16_rn(x);
    return *reinterpret_cast<unsigned short*>(&h);
}
__device__ __forceinline__ float bf2f(unsigned short u) {
    __nv_bfloat16 h = *reinterpret_cast<__nv_bfloat16*>(&u);
    return __bfloat162float(h);
}
__device__ __forceinline__ uint32_t pack_bf2(float a, float b) {
    return (uint32_t)f2bf(a) | ((uint32_t)f2bf(b) << 16);
}

__device__ __forceinline__ void mma8(float c[4], uint32_t a0, uint32_t a1, uint32_t b0) {
    asm volatile(
        "mma.sync.aligned.m16n8k8.row.col.f32.bf16.bf16.f32 "
        "{%0,%1,%2,%3}, {%4,%5}, {%6}, {%0,%1,%2,%3};"
        : "+f"(c[0]), "+f"(c[1]), "+f"(c[2]), "+f"(c[3])
        : "r"(a0), "r"(a1), "r"(b0));
}
__device__ __forceinline__ void mma16(float c[4], uint32_t a0, uint32_t a1,
                                      uint32_t a2, uint32_t a3,
                                      uint32_t b0, uint32_t b1) {
    asm volatile(
        "mma.sync.aligned.m16n8k16.row.col.f32.bf16.bf16.f32 "
        "{%0,%1,%2,%3}, {%4,%5,%6,%7}, {%8,%9}, {%0,%1,%2,%3};"
        : "+f"(c[0]), "+f"(c[1]), "+f"(c[2]), "+f"(c[3])
        : "r"(a0), "r"(a1), "r"(a2), "r"(a3), "r"(b0), "r"(b1));
}

// permuted A slot (u32 index) for element (m-tile mt, row-in-tile r16, col c)
__device__ __forceinline__ int a_slot(int mt, int r16, int c) {
    int regr = (r16 >= 8) ? 1 : 0;
    int lb = (r16 & 7) * 4;
    if (c < 144) {
        int ks = c >> 4, kc = c & 15;
        return mt * 1216 + ks * 128 + (lb + ((kc & 7) >> 1)) * 4 + regr + ((kc >= 8) ? 2 : 0);
    } else {
        int kc = c - 144;
        return mt * 1216 + 1152 + (lb + (kc >> 1)) * 2 + regr;
    }
}

// =======================================================================
// K1 : scan + means (+ weight cvt / W1 prefetch) + GEMM1 + pair build
// =======================================================================
#define NT1 1024
#define OFF_P   0
#define OFF_MT  30880
#define OFF_G   37024
#define OFF_B1  38240
#define OFF_BND 38392
#define SM1_FLOATS 38408
#define SM1_BYTES (SM1_FLOATS * 4)

__global__ __launch_bounds__(NT1, 1)
void grapher_k1(const int* __restrict__ ids,
                const float* __restrict__ feat,
                const float* __restrict__ W1, const float* __restrict__ b1,
                const float* __restrict__ Wm, const float* __restrict__ W2)
{
    extern __shared__ float sm[];
    float* sP  = sm + OFF_P;
    float* sMT = sm + OFF_MT;
    float* sG  = sm + OFF_G;
    float* sB1 = sm + OFF_B1;
    int*   sBnd = (int*)(sm + OFF_BND);

    const int tid = threadIdx.x;
    const int b   = blockIdx.x;
    const uint32_t mt_b = sptr(sMT);
    const uint32_t pp_b = sptr(sP);

    // ---- scan (warp 0) + b1 load ----
    if (tid < 32) {
        const int lane = tid;
        if (lane < 16) sBnd[lane] = S_;
        __syncwarp();
        const int4* rp = (const int4*)(ids + (size_t)b * S_) + lane * 8;
        int4 v[8];
        int cnt = 0;
#pragma unroll
        for (int q = 0; q < 8; q++) {
            v[q] = rp[q];
            cnt += (v[q].x == SEPID) + (v[q].y == SEPID) +
                   (v[q].z == SEPID) + (v[q].w == SEPID);
        }
        int pre = cnt;
#pragma unroll
        for (int off = 1; off < 32; off <<= 1) {
            int t = __shfl_up_sync(0xffffffffu, pre, off);
            if (lane >= off) pre += t;
        }
        int run = pre - cnt;
#pragma unroll
        for (int q = 0; q < 8; q++) {
            int base = lane * 32 + q * 4;
            if (v[q].x == SEPID) { run++; if (run <= NN) sBnd[run] = base + 0; }
            if (v[q].y == SEPID) { run++; if (run <= NN) sBnd[run] = base + 1; }
            if (v[q].z == SEPID) { run++; if (run <= NN) sBnd[run] = base + 2; }
            if (v[q].w == SEPID) { run++; if (run <= NN) sBnd[run] = base + 3; }
        }
    } else if (tid >= 64 && tid < 64 + 152) {
        int i = tid - 64;
        sB1[i] = (i < C_) ? b1[i] : 0.f;
    }
    __syncthreads();

    // ---- means partials (tid<960) || weight cvt / W1 prefetch (spares) ----
    if (tid < 960) {
        const int tg  = tid / 192;
        const int col = tid - tg * 192;
        const int T   = sBnd[NN];
        const int tb0 = (T * tg) / 5;
        const int tb1 = (T * (tg + 1)) / 5;
        const float4* f4 = (const float4*)(feat + (size_t)b * S_ * H_) + col;
        float* P = sP + tg * 6176 + col * 4;
#pragma unroll 1
        for (int n = 0; n < NN; n++) {
            int lo = (n == 0) ? 0 : sBnd[n] + 1;
            int hi = sBnd[n + 1];
            if (lo < tb0) lo = tb0;
            if (hi > tb1) hi = tb1;
            float4 a0 = make_float4(0.f, 0.f, 0.f, 0.f), a1 = a0, a2 = a0, a3 = a0;
            int t = lo;
            for (; t + 3 < hi; t += 4) {
                float4 v0 = f4[(t + 0) * 192];
                float4 v1 = f4[(t + 1) * 192];
                float4 v2 = f4[(t + 2) * 192];
                float4 v3 = f4[(t + 3) * 192];
                a0.x += v0.x; a0.y += v0.y; a0.z += v0.z; a0.w += v0.w;
                a1.x += v1.x; a1.y += v1.y; a1.z += v1.z; a1.w += v1.w;
                a2.x += v2.x; a2.y += v2.y; a2.z += v2.z; a2.w += v2.w;
                a3.x += v3.x; a3.y += v3.y; a3.z += v3.z; a3.w += v3.w;
            }
            for (; t < hi; t++) {
                float4 v = f4[t * 192];
                a0.x += v.x; a0.y += v.y; a0.z += v.z; a0.w += v.w;
            }
            float4 s;
            s.x = (a0.x + a1.x) + (a2.x + a3.x);
            s.y = (a0.y + a1.y) + (a2.y + a3.y);
            s.z = (a0.z + a1.z) + (a2.z + a3.z);
            s.w = (a0.w + a1.w) + (a2.w + a3.w);
            *(float4*)(P + n * 772) = s;
        }
    } else if (b < 38) {
        // blocks 0-37: convert Wm/W2 -> permuted g_Wcvt
        const int start = b * 64 + (tid - 960);          // 0..2431
#pragma unroll
        for (int q = 0; q < 19; q++) {
            int idx = start + q * 2432;                  // < 46208
            int layer = idx / (152 * 152);
            int rem = idx - layer * 152 * 152;
            int n = rem / 152, k = rem - n * 152;
            const float* src = layer ? W2 : Wm;
            float v = (k < C_ && n < C_) ? __ldg(src + k * C_ + n) : 0.f;
            unsigned short h = f2bf(v);
            unsigned short l = f2bf(v - bf2f(h));
            int jj = n >> 3, ng = n & 7;
            int au, half = k & 1;
            if (k < 144) {
                int ks = k >> 4, kc = k & 15;
                au = jj * 608 + ks * 64 + (ng * 4 + ((kc & 7) >> 1)) * 2 + ((kc >= 8) ? 1 : 0);
            } else {
                int kc = k - 144;
                au = jj * 608 + 576 + ng * 4 + (kc >> 1);
            }
            int base = layer * 2 * W_IMG_HALF;
            g_Wcvt[base + au * 2 + half] = h;
            g_Wcvt[base + W_IMG_HALF + au * 2 + half] = l;
        }
    } else {
        const float4* w4 = (const float4*)W1;
        for (int i = tid - 960; i < (H_ * C_) / 4; i += 64)
            asm volatile("prefetch.global.L2 [%0];" :: "l"(w4 + i));
    }
    __syncthreads();

    // ---- combine tiles + 1/len -> meansT[k][8] ----
    if (tid < H_) {
        float inv[8];
#pragma unroll
        for (int n = 0; n < NN; n++) {
            int lo = (n == 0) ? 0 : sBnd[n] + 1;
            int len = sBnd[n + 1] - lo;
            if (len < 1) len = 1;
            inv[n] = 1.0f / (float)len;
        }
        const float* P = sP + tid;
#pragma unroll
        for (int n = 0; n < NN; n++) {
            float s = ((P[n * 772] + P[6176 + n * 772]) +
                       (P[12352 + n * 772] + P[18528 + n * 772])) + P[24704 + n * 772];
            sMT[tid * 8 + n] = s * inv[n];
        }
    }
    __syncthreads();

    // ---- GEMM1 (fp32 FFMA2): g[n][c] = sum_k meansT[k][n] * W1[k][c] ----
    u64 g_acc[2][4];
    int ks1 = 0, cpair = 0;
    if (tid < 600) {
        ks1 = tid / 75; cpair = tid - ks1 * 75;
#pragma unroll
        for (int cc = 0; cc < 2; cc++)
#pragma unroll
            for (int q = 0; q < 4; q++) g_acc[cc][q] = 0ull;
        const float2* wrow = (const float2*)(W1 + (size_t)(ks1 * 96) * C_) + cpair;
#pragma unroll 4
        for (int kk = 0; kk < 96; kk++) {
            int k = ks1 * 96 + kk;
            float2 w = __ldg(wrow + kk * 75);
            u64 dw0 = dup2(w.x), dw1 = dup2(w.y);
            u64 m01, m23, m45, m67;
            uint32_t ma = mt_b + (uint32_t)(k * 8) * 4u;
            lds_v2(ma, m01, m23);
            lds_v2(ma + 16u, m45, m67);
            ffma2(g_acc[0][0], m01, dw0); ffma2(g_acc[0][1], m23, dw0);
            ffma2(g_acc[0][2], m45, dw0); ffma2(g_acc[0][3], m67, dw0);
            ffma2(g_acc[1][0], m01, dw1); ffma2(g_acc[1][1], m23, dw1);
            ffma2(g_acc[1][2], m45, dw1); ffma2(g_acc[1][3], m67, dw1);
        }
    }
    __syncthreads();
    if (tid < 600) {
#pragma unroll
        for (int cc = 0; cc < 2; cc++)
#pragma unroll
            for (int q = 0; q < 4; q++)
                sts64(pp_b + (uint32_t)(ks1 * 1200 + (cc * 4 + q) * 150 + 2 * cpair) * 4u,
                      g_acc[cc][q]);
    }
    __syncthreads();
    if (tid < 600) {
        u64 s = lds64(pp_b + (uint32_t)(2 * tid) * 4u);
#pragma unroll
        for (int k8 = 1; k8 < 8; k8++)
            s = add2(s, lds64(pp_b + (uint32_t)(k8 * 1200 + 2 * tid) * 4u));
        int e = tid / 75, cp2 = tid - e * 75;
        int cc = e >> 2, q = e & 3, c = 2 * cp2 + cc;
        float lo, hi; unpack2(s, lo, hi);
        sG[(2 * q + 0) * 152 + c] = lo;
        sG[(2 * q + 1) * 152 + c] = hi;
    }
    __syncthreads();

    // ---- pair build -> permuted g_Ximg[b] ----
    {
        const int p  = tid >> 4;          // 0..63
        const int cs = tid & 15;          // col segment of 10
        const int i  = p >> 3, j = p & 7;
        const int mt = p >> 4;
        const int r16 = p & 15;
        uint32_t* dhi = g_Ximg + (size_t)b * 9728;
        uint32_t* dlo = dhi + 4864;
#pragma unroll
        for (int m = 0; m < 5; m++) {
            int c = cs * 10 + 2 * m;
            if (c < 152) {
                float v0 = 0.f, v1 = 0.f;
                if (c < C_)
                    v0 = fmaxf(sG[i * 152 + c] - sG[j * 152 + c] + sB1[c], 0.f);
                if (c + 1 < C_)
                    v1 = fmaxf(sG[i * 152 + c + 1] - sG[j * 152 + c + 1] + sB1[c + 1], 0.f);
                unsigned short h0 = f2bf(v0), h1 = f2bf(v1);
                int slot = a_slot(mt, r16, c);
                dhi[slot] = (uint32_t)h0 | ((uint32_t)h1 << 16);
                dlo[slot] = pack_bf2(v0 - bf2f(h0), v1 - bf2f(h1));
            }
        }
    }
}

// =======================================================================
// K2 : tensor-core 2-layer MLP (per batch), permuted fragment loads
// =======================================================================
#define NT2 608
#define O_WMHI 0
#define O_WMLO 46208
#define O_W2HI 92416
#define O_W2LO 138624
#define O_X    184832     // permuted Xhi (19456 B)
#define O_XLO  204288     // permuted Xlo
#define SM2_BYTES 223744

__global__ __launch_bounds__(NT2, 1)
void grapher_k2(const float* __restrict__ bm, const float* __restrict__ b2,
                float* __restrict__ out)
{
    extern __shared__ char smc[];
    const uint32_t sb = sptr(smc);
    const int tid = threadIdx.x;
    const int b   = blockIdx.x;

    // ---- group A: Wm hi/lo + X image ----
    {
        const uint4* wsrc = (const uint4*)g_Wcvt;
        const uint4* xsrc = (const uint4*)(g_Ximg + (size_t)b * 9728);
        for (int i = tid; i < 8208; i += NT2) {
            if (i < 5776) cp16(sb + O_WMHI + (uint32_t)i * 16u, wsrc + i);
            else          cp16(sb + O_X + (uint32_t)(i - 5776) * 16u, xsrc + (i - 5776));
        }
        CP_COMMIT();
        for (int i = tid; i < 5776; i += NT2)
            cp16(sb + O_W2HI + (uint32_t)i * 16u, wsrc + 5776 + i);
        CP_COMMIT();
    }

    const int lane = tid & 31;
    const int g    = lane >> 2;
    const int tg   = lane & 3;
    const int j19  = tid >> 5;            // warp's n8 tile
    const int cc0  = j19 * 8 + 2 * tg;

    CP_WAIT1();
    __syncthreads();

    float acc[4][4];

#pragma unroll 1
    for (int L = 0; L < 2; L++) {
        const uint32_t whb = sb + (L ? O_W2HI : O_WMHI);
        const uint32_t wlb = sb + (L ? O_W2LO : O_WMLO);
        const float* bias = L ? b2 : bm;
        {
            float bv0 = (cc0 < C_)     ? __ldg(bias + cc0)     : 0.f;
            float bv1 = (cc0 + 1 < C_) ? __ldg(bias + cc0 + 1) : 0.f;
#pragma unroll
            for (int mt = 0; mt < 4; mt++) {
                acc[mt][0] = bv0; acc[mt][1] = bv1;
                acc[mt][2] = bv0; acc[mt][3] = bv1;
            }
        }
        const uint32_t bh_base = whb + (uint32_t)(j19 * 608 + lane * 2) * 4u;
        const uint32_t bl_base = wlb + (uint32_t)(j19 * 608 + lane * 2) * 4u;
        const uint32_t ah_base = sb + O_X   + (uint32_t)(lane * 4) * 4u;
        const uint32_t al_base = sb + O_XLO + (uint32_t)(lane * 4) * 4u;

#pragma unroll 3
        for (int ks = 0; ks < 9; ks++) {
            uint32_t bh0, bh1, bl0, bl1;
            lds_v2u32(bh_base + (uint32_t)(ks * 64) * 4u, bh0, bh1);
            lds_v2u32(bl_base + (uint32_t)(ks * 64) * 4u, bl0, bl1);
#pragma unroll
            for (int mt = 0; mt < 4; mt++) {
                uint32_t off = (uint32_t)((mt * 1216 + ks * 128) * 4);
                uint32_t ah0, ah1, ah2, ah3, al0, al1, al2, al3;
                lds_v4u32(ah_base + off, ah0, ah1, ah2, ah3);
                lds_v4u32(al_base + off, al0, al1, al2, al3);
                mma16(acc[mt], ah0, ah1, ah2, ah3, bh0, bh1);
                mma16(acc[mt], ah0, ah1, ah2, ah3, bl0, bl1);
                mma16(acc[mt], al0, al1, al2, al3, bh0, bh1);
            }
        }
        {   // k8 tail
            uint32_t bh = lds_u32(whb + (uint32_t)(j19 * 608 + 576 + lane) * 4u);
            uint32_t bl = lds_u32(wlb + (uint32_t)(j19 * 608 + 576 + lane) * 4u);
#pragma unroll
            for (int mt = 0; mt < 4; mt++) {
                uint32_t off = (uint32_t)((mt * 1216 + 1152 + lane * 2) * 4);
                uint32_t ah0, ah1, al0, al1;
                lds_v2u32(sb + O_X   + off, ah0, ah1);
                lds_v2u32(sb + O_XLO + off, al0, al1);
                mma8(acc[mt], ah0, ah1, bh);
                mma8(acc[mt], ah0, ah1, bl);
                mma8(acc[mt], al0, al1, bh);
            }
        }
        __syncthreads();

        if (L == 0) {
            // y = relu(acc) -> re-split into permuted Xhi/Xlo slots
            int sa, sbs;
            if (cc0 < 144) {
                int ks2 = cc0 >> 4, kc = cc0 & 15;
                sa = ks2 * 128 + (g * 4 + ((kc & 7) >> 1)) * 4 + ((kc >= 8) ? 2 : 0);
            } else {
                int kc = cc0 - 144;
                sa = 1152 + (g * 4 + (kc >> 1)) * 2;
            }
            sbs = sa + 1;   // row g+8 slot
#pragma unroll
            for (int mt = 0; mt < 4; mt++) {
                float y00 = fmaxf(acc[mt][0], 0.f), y01 = fmaxf(acc[mt][1], 0.f);
                float y10 = fmaxf(acc[mt][2], 0.f), y11 = fmaxf(acc[mt][3], 0.f);
                unsigned short h00 = f2bf(y00), h01 = f2bf(y01);
                unsigned short h10 = f2bf(y10), h11 = f2bf(y11);
                uint32_t oa = (uint32_t)(mt * 1216 + sa) * 4u;
                uint32_t ob = (uint32_t)(mt * 1216 + sbs) * 4u;
                sts_u32(sb + O_X   + oa, (uint32_t)h00 | ((uint32_t)h01 << 16));
                sts_u32(sb + O_X   + ob, (uint32_t)h10 | ((uint32_t)h11 << 16));
                sts_u32(sb + O_XLO + oa, pack_bf2(y00 - bf2f(h00), y01 - bf2f(h01)));
                sts_u32(sb + O_XLO + ob, pack_bf2(y10 - bf2f(h10), y11 - bf2f(h11)));
            }
            CP_WAIT0();
            __syncthreads();
        }
    }

    // ---------- output ----------
    if (cc0 < C_) {
#pragma unroll
        for (int mt = 0; mt < 4; mt++) {
            int p0 = mt * 16 + g, p1 = p0 + 8;
            float* o0 = out + ((size_t)p0 * B_ + b) * C_ + cc0;
            float* o1 = out + ((size_t)p1 * B_ + b) * C_ + cc0;
            *(float2*)o0 = make_float2(acc[mt][0], acc[mt][1]);
            *(float2*)o1 = make_float2(acc[mt][2], acc[mt][3]);
        }
    }
}

// =======================================================================
extern "C" void kernel_launch(void* const* d_in, const int* in_sizes, int n_in,
                              void* d_out, int out_size)
{
    const int*   ids  = (const int*)d_in[0];
    const float* feat = (const float*)d_in[1];
    const float* W1 = (const float*)d_in[2];
    const float* b1 = (const float*)d_in[3];
    const float* Wm = (const float*)d_in[4];
    const float* bm = (const float*)d_in[5];
    const float* W2 = (const float*)d_in[6];
    const float* b2 = (const float*)d_in[7];
    float* out = (float*)d_out;

    cudaFuncSetAttribute(grapher_k1, cudaFuncAttributeMaxDynamicSharedMemorySize, SM1_BYTES);
    cudaFuncSetAttribute(grapher_k2, cudaFuncAttributeMaxDynamicSharedMemorySize, SM2_BYTES);

    grapher_k1<<<B_, NT1, SM1_BYTES>>>(ids, feat, W1, b1, Wm, W2);
    grapher_k2<<<B_, NT2, SM2_BYTES>>>(bm, b2, out);
}